// round 14
// baseline (speedup 1.0000x reference)
#include <cuda_runtime.h>
#include <cuda_bf16.h>
#include <cuda_fp16.h>
#include <cstdint>

#define HIDDEN 1024
#define HEADS  16
#define HDIM   64
#define RANK   16
#define SEQ    2048
#define BS     4
#define NTOK   (BS*SEQ)          /* 8192 */
#define NBH    (BS*HEADS)        /* 64 */
#define LOG2E  1.44269504088896340736f
#define ONES2  0x3C003C00u       /* f16x2 {1.0, 1.0} */

// ---------------- scratch (device globals; no allocation) -------------------
__device__ __align__(16) __half g_xh[(size_t)NTOK*HIDDEN];
__device__ __align__(16) __half g_wh[(size_t)3*HIDDEN*HIDDEN];
// Q (pre-scaled by 0.125*log2e), K, V: all single fp16, [bh][seq][64].
__device__ __align__(16) __half gQh[(size_t)NBH*SEQ*HDIM];
__device__ __align__(16) __half gKh[(size_t)NBH*SEQ*HDIM];
__device__ __align__(16) __half gVh[(size_t)NBH*SEQ*HDIM];

// ---------------- low-level helpers ----------------------------------------
__device__ __forceinline__ uint32_t smem_u32(const void* p) {
    uint32_t a;
    asm("{ .reg .u64 t; cvta.to.shared.u64 t, %1; cvt.u32.u64 %0, t; }"
        : "=r"(a) : "l"(p));
    return a;
}
__device__ __forceinline__ void cpa16(uint32_t dst, const void* src) {
    asm volatile("cp.async.cg.shared.global [%0],[%1],16;"
                 :: "r"(dst), "l"(__cvta_generic_to_global(src)));
}
#define CP_COMMIT() asm volatile("cp.async.commit_group;" ::: "memory")
#define CP_WAIT(n)  asm volatile("cp.async.wait_group %0;" :: "n"(n) : "memory")

#define SWZ(o)   ((o) ^ (((o) >> 3) & 0x70))   /* 128B rows */

__device__ __forceinline__ void ldsm4(uint32_t r[4], uint32_t a) {
    asm volatile("ldmatrix.sync.aligned.m8n8.x4.shared.b16 {%0,%1,%2,%3},[%4];"
        : "=r"(r[0]), "=r"(r[1]), "=r"(r[2]), "=r"(r[3]) : "r"(a));
}
__device__ __forceinline__ void ldsm4t(uint32_t r[4], uint32_t a) {
    asm volatile("ldmatrix.sync.aligned.m8n8.x4.trans.shared.b16 {%0,%1,%2,%3},[%4];"
        : "=r"(r[0]), "=r"(r[1]), "=r"(r[2]), "=r"(r[3]) : "r"(a));
}
// fp16 MMA
__device__ __forceinline__ void mma16816h(float c[4], const uint32_t a[4],
                                          uint32_t b0, uint32_t b1) {
    asm volatile(
        "mma.sync.aligned.m16n8k16.row.col.f32.f16.f16.f32 "
        "{%0,%1,%2,%3},{%4,%5,%6,%7},{%8,%9},{%0,%1,%2,%3};"
        : "+f"(c[0]), "+f"(c[1]), "+f"(c[2]), "+f"(c[3])
        : "r"(a[0]), "r"(a[1]), "r"(a[2]), "r"(a[3]), "r"(b0), "r"(b1));
}
__device__ __forceinline__ uint32_t pkhf(float x, float y) {
    uint32_t r;
    asm("cvt.rn.f16x2.f32 %0,%1,%2;" : "=r"(r) : "f"(y), "f"(x));
    return r;
}
__device__ __forceinline__ uint32_t hadd2(uint32_t a, uint32_t b) {
    uint32_t r;
    asm("add.f16x2 %0,%1,%2;" : "=r"(r) : "r"(a), "r"(b));
    return r;
}
__device__ __forceinline__ uint32_t ex2h2(uint32_t x) {
    uint32_t r;
    asm("ex2.approx.f16x2 %0,%1;" : "=r"(r) : "r"(x));
    return r;
}

// ---------------------------------------------------------------------------
// Kernel 1a: convert X to fp16.
// ---------------------------------------------------------------------------
__global__ void xsplit_kernel(const float* __restrict__ X) {
    size_t i = ((size_t)blockIdx.x * 256 + threadIdx.x) * 4;
    float4 v = *(const float4*)&X[i];
    *(uint2*)&g_xh[i] = make_uint2(pkhf(v.x, v.y), pkhf(v.z, v.w));
}

// ---------------------------------------------------------------------------
// Kernel 1b (fused): Weff = W + (1/16) B @ A, stored as single fp16.
// ---------------------------------------------------------------------------
__global__ void wsplit_kernel(
        const float* __restrict__ Wq, const float* __restrict__ Aq, const float* __restrict__ Bq,
        const float* __restrict__ Wk, const float* __restrict__ Ak, const float* __restrict__ Bk,
        const float* __restrict__ Wv, const float* __restrict__ Av, const float* __restrict__ Bv) {
    int p = blockIdx.y;
    const float* W = (p == 0) ? Wq : ((p == 1) ? Wk : Wv);
    const float* A = (p == 0) ? Aq : ((p == 1) ? Ak : Av);
    const float* B = (p == 0) ? Bq : ((p == 1) ? Bk : Bv);
    int n = blockIdx.x;
    __shared__ float Brow[RANK];
    if (threadIdx.x < RANK)
        Brow[threadIdx.x] = B[n*RANK + threadIdx.x] * (1.0f/RANK);
    __syncthreads();
    size_t roff = ((size_t)p*HIDDEN + n) * HIDDEN;
    const float* wr = W + (size_t)n*HIDDEN;
    for (int k = threadIdx.x; k < HIDDEN; k += blockDim.x) {
        float acc = wr[k];
        #pragma unroll
        for (int r = 0; r < RANK; r++)
            acc += Brow[r] * A[r*HIDDEN + k];
        g_wh[roff + k] = __float2half_rn(acc);
    }
}

// ---------------------------------------------------------------------------
// Kernel 2: QKV GEMM, fp16 single-term, tile 256x128, K-chunk 64, 2-stage,
// 512 threads (16 warps = 4m x 4n), 1 CTA/SM.
// ---------------------------------------------------------------------------
#define GXT 32768                    /* X tile: 256 rows x 64 fp16 (128B rows) */
#define GWT 16384                    /* W tile: 128 rows x 64 fp16 */
#define GSTAGE (GXT + GWT)           /* 48 KB */
#define GEMM_SMEM (2*GSTAGE)         /* 96 KB (>= epilogue 67584B) */

__global__ __launch_bounds__(512, 1) void qkv_gemm_mma(
        const float* __restrict__ bq,
        const float* __restrict__ bk,
        const float* __restrict__ bv) {
    extern __shared__ char smg[];
    uint32_t sb = smem_u32(smg);
    int tid = threadIdx.x, lane = tid & 31, wid = tid >> 5;
    int bm = blockIdx.y * 256, bn = blockIdx.x * 128;
    int wm = (wid >> 2) * 64, wn = (wid & 3) * 32;

    float acc[4][4][4];
    #pragma unroll
    for (int a = 0; a < 4; a++)
        #pragma unroll
        for (int b = 0; b < 4; b++)
            #pragma unroll
            for (int c = 0; c < 4; c++) acc[a][b][c] = 0.0f;

    auto load_stage = [&](int s, int c) {
        int k0 = c * 64;
        uint32_t base = sb + s * GSTAGE;
        // X: 256 rows x 8 chunks = 2048; 512 thr x 4
        #pragma unroll
        for (int it = 0; it < 4; it++) {
            int idx = tid + it*512;
            int r = idx >> 3, cb = (idx & 7) << 4;
            uint32_t so = SWZ(r*128 + cb);
            cpa16(base + so, (const char*)(g_xh + (size_t)(bm + r)*HIDDEN + k0) + cb);
        }
        // W: 128 rows x 8 chunks = 1024; 512 thr x 2
        #pragma unroll
        for (int it = 0; it < 2; it++) {
            int idx = tid + it*512;
            int r = idx >> 3, cb = (idx & 7) << 4;
            uint32_t so = SWZ(r*128 + cb);
            cpa16(base + GXT + so, (const char*)(g_wh + (size_t)(bn + r)*HIDDEN + k0) + cb);
        }
    };

    load_stage(0, 0); CP_COMMIT();

    for (int c = 0; c < 16; c++) {
        CP_WAIT(0);
        __syncthreads();
        if (c + 1 < 16) { load_stage((c + 1) & 1, c + 1); CP_COMMIT(); }

        uint32_t tb = sb + (c & 1) * GSTAGE;
        int arow = wm + (lane & 15);
        int bro  = wn + ((lane >> 4) & 1)*8 + (lane & 7);
        #pragma unroll
        for (int ks = 0; ks < 4; ks++) {
            int acb = ks*32 + ((lane >> 4) & 1)*16;
            int bcb = ks*32 + ((lane >> 3) & 1)*16;
            uint32_t ah[4][4];
            #pragma unroll
            for (int mt = 0; mt < 4; mt++)
                ldsm4(ah[mt], tb + SWZ((arow + mt*16)*128 + acb));
            #pragma unroll
            for (int nt2 = 0; nt2 < 2; nt2++) {
                uint32_t bh4[4];
                ldsm4(bh4, tb + GXT + SWZ((bro + nt2*16)*128 + bcb));
                #pragma unroll
                for (int mt = 0; mt < 4; mt++) {
                    mma16816h(acc[mt][nt2*2],   ah[mt], bh4[0], bh4[1]);
                    mma16816h(acc[mt][nt2*2+1], ah[mt], bh4[2], bh4[3]);
                }
            }
        }
    }
    __syncthreads();   // all reads of stage smem done before epilogue reuse

    int p    = bn >> 10;
    int coff = bn & 1023;
    const float* bias = (p == 0) ? bq : ((p == 1) ? bk : bv);
    float scale = (p == 0) ? 0.125f * LOG2E : 1.0f;
    __half* dst = (p == 0) ? gQh : ((p == 1) ? gKh : gVh);

    float* st = (float*)smg;
    int r0 = lane >> 2, col0 = (lane & 3)*2;

    // two 128-row passes through a 128x132 f32 staging buffer
    #pragma unroll
    for (int pass = 0; pass < 2; pass++) {
        if ((wm >> 7) == pass) {
            int wml = wm & 127;  // FIXED (was & 63: wm=64 collided with wm=0)
            #pragma unroll
            for (int mt = 0; mt < 4; mt++)
                #pragma unroll
                for (int nt = 0; nt < 4; nt++) {
                    int rr = wml + mt*16 + r0;
                    int cc = wn + nt*8 + col0;
                    *(float2*)&st[(size_t)rr*132 + cc] =
                        make_float2(acc[mt][nt][0], acc[mt][nt][1]);
                    *(float2*)&st[(size_t)(rr + 8)*132 + cc] =
                        make_float2(acc[mt][nt][2], acc[mt][nt][3]);
                }
        }
        __syncthreads();

        #pragma unroll
        for (int it = 0; it < 8; it++) {
            int idx = tid + it*512;
            int r = idx >> 5, c4 = (idx & 31)*4;
            float4 v = *(float4*)&st[(size_t)r*132 + c4];
            int colg = coff + c4;
            float4 bi = *(const float4*)&bias[colg];
            v.x = (v.x + bi.x)*scale; v.y = (v.y + bi.y)*scale;
            v.z = (v.z + bi.z)*scale; v.w = (v.w + bi.w)*scale;
            int m  = bm + pass*128 + r;
            int bb = m >> 11, sq = m & 2047;
            int h  = colg >> 6, d = colg & 63;
            size_t o = ((size_t)(bb*HEADS + h)*SEQ + sq)*HDIM + d;
            *(uint2*)&dst[o] = make_uint2(pkhf(v.x, v.y), pkhf(v.z, v.w));
        }
        __syncthreads();
    }
}

// ---------------------------------------------------------------------------
// Kernel 3: flash attention, kv-chunk 128 (2-stage), no-max softmax,
// f16x2 exponent path interleaved with PV per kt, l via ones-MMA. 2 CTAs/SM.
// ---------------------------------------------------------------------------
#define AKT2 16384                    /* one 128x64 fp16 KV tile */
#define AQT 16384                     /* one 128x64 fp16 Q tile */
#define AT_Q 4096                     /* after 4KB fp16 mask */
#define AT_KV (AT_Q + AQT)            /* 20480 */
#define AT_STG (2*AKT2)               /* 32768: Kh,Vh */
#define AT_SMEM (AT_KV + 2*AT_STG)    /* 86016 */

__global__ __launch_bounds__(256, 2) void attn_mma(
        const float* __restrict__ mask,
        float* __restrict__ out) {
    extern __shared__ char sma[];
    uint32_t sb = smem_u32(sma);
    int tid = threadIdx.x, lane = tid & 31, wid = tid >> 5;
    int bh = blockIdx.y;
    int b = bh >> 4, h = bh & 15;
    int q0 = blockIdx.x * 128;

    // mask row -> smem as f16x2, premultiplied by log2e
    __half* Msh = (__half*)sma;
    #pragma unroll
    for (int it = 0; it < 2; it++) {
        int i4 = (tid + it*256)*4;
        float4 v = *(const float4*)&mask[(size_t)b*SEQ + i4];
        *(uint32_t*)&Msh[i4]   = pkhf(v.x*LOG2E, v.y*LOG2E);
        *(uint32_t*)&Msh[i4+2] = pkhf(v.z*LOG2E, v.w*LOG2E);
    }
    // Q tile (128x64 fp16) -> smem
    {
        const char* qh = (const char*)(gQh + ((size_t)bh*SEQ + q0)*HDIM);
        #pragma unroll
        for (int it = 0; it < 4; it++) {
            int idx = tid + it*256;
            int r = idx >> 3, cb = (idx & 7) << 4;
            uint32_t so = SWZ(r*128 + cb);
            *(uint4*)(sma + AT_Q + so) = *(const uint4*)(qh + r*128 + cb);
        }
    }

    auto load_kv = [&](int s, int c) {
        size_t roff = ((size_t)bh*SEQ + c*128)*HDIM;
        uint32_t base = sb + AT_KV + s*AT_STG;
        const char* kh = (const char*)(gKh + roff);
        const char* vh = (const char*)(gVh + roff);
        #pragma unroll
        for (int it = 0; it < 4; it++) {
            int idx = tid + it*256;
            int r = idx >> 3, cb = (idx & 7) << 4;
            uint32_t so = SWZ(r*128 + cb);
            cpa16(base + so,        kh + r*128 + cb);
            cpa16(base + AKT2 + so, vh + r*128 + cb);
        }
    };

    load_kv(0, 0); CP_COMMIT();
    __syncthreads();   // Q + mask visible

    // persistent Q fragments (16 regs)
    uint32_t qf[4][4];
    {
        int arow = wid*16 + (lane & 15);
        #pragma unroll
        for (int ks = 0; ks < 4; ks++) {
            int acb = ks*32 + ((lane >> 4) & 1)*16;
            ldsm4(qf[ks], sb + AT_Q + SWZ(arow*128 + acb));
        }
    }

    float o[8][4];
    #pragma unroll
    for (int i = 0; i < 8; i++)
        #pragma unroll
        for (int j = 0; j < 4; j++) o[i][j] = 0.0f;
    float lsum[4] = {0.0f, 0.0f, 0.0f, 0.0f};   // ones-MMA row sums

    int bro  = (lane & 7) + ((lane >> 4) & 1)*8;
    int col0 = (lane & 3)*2;

    for (int c = 0; c < 16; c++) {
        CP_WAIT(0);
        __syncthreads();
        if (c + 1 < 16) { load_kv((c + 1) & 1, c + 1); CP_COMMIT(); }

        uint32_t stg = sb + AT_KV + (c & 1)*AT_STG;

        #pragma unroll
        for (int half = 0; half < 2; half++) {
            uint32_t kb = stg + half*8192;            // 64 rows x 128B
            uint32_t vb = stg + AKT2 + half*8192;

            // ---- S = Q K^T : fp16, single term ----
            float sc[8][4];
            #pragma unroll
            for (int i = 0; i < 8; i++)
                #pragma unroll
                for (int j = 0; j < 4; j++) sc[i][j] = 0.0f;

            #pragma unroll
            for (int ks = 0; ks < 4; ks++) {
                int bcb = ks*32 + ((lane >> 3) & 1)*16;
                uint32_t kh4[4][4];
                #pragma unroll
                for (int nt2 = 0; nt2 < 4; nt2++)
                    ldsm4(kh4[nt2], kb + SWZ((nt2*16 + bro)*128 + bcb));
                #pragma unroll
                for (int nt2 = 0; nt2 < 4; nt2++) {
                    mma16816h(sc[nt2*2],   qf[ks], kh4[nt2][0], kh4[nt2][1]);
                    mma16816h(sc[nt2*2+1], qf[ks], kh4[nt2][2], kh4[nt2][3]);
                }
            }

            // ---- per-kt: P = 2^(s+mask) (f16x2), lsum MMA, then PV ----
            int ckv = c*128 + half*64;
            #pragma unroll
            for (int kt = 0; kt < 4; kt++) {
                float* e = sc[2*kt];
                float* f = sc[2*kt+1];
                uint32_t mk0 = *(uint32_t*)&Msh[ckv + kt*16 + col0];
                uint32_t mk1 = *(uint32_t*)&Msh[ckv + kt*16 + 8 + col0];
                uint32_t ph[4];
                ph[0] = ex2h2(hadd2(pkhf(e[0], e[1]), mk0));
                ph[1] = ex2h2(hadd2(pkhf(e[2], e[3]), mk0));
                ph[2] = ex2h2(hadd2(pkhf(f[0], f[1]), mk1));
                ph[3] = ex2h2(hadd2(pkhf(f[2], f[3]), mk1));
                mma16816h(lsum, ph, ONES2, ONES2);

                int vrow = kt*16 + (lane & 15);
                uint32_t vh4[4][4];
                #pragma unroll
                for (int dt2 = 0; dt2 < 4; dt2++) {
                    int vcb = dt2*32 + ((lane >> 4) & 1)*16;
                    ldsm4t(vh4[dt2], vb + SWZ(vrow*128 + vcb));
                }
                #pragma unroll
                for (int dt2 = 0; dt2 < 4; dt2++) {
                    mma16816h(o[dt2*2],   ph, vh4[dt2][0], vh4[dt2][1]);
                    mma16816h(o[dt2*2+1], ph, vh4[dt2][2], vh4[dt2][3]);
                }
            }
        }
    }
    __syncthreads();   // all smem reads done before epilogue reuse

    // ---- epilogue: normalize, stage (128x68 f32), write ----
    float inv0 = 1.0f / lsum[0], inv1 = 1.0f / lsum[2];
    float* Ost = (float*)sma;
    int r0 = wid*16 + (lane >> 2);
    #pragma unroll
    for (int nt = 0; nt < 8; nt++) {
        *(float2*)&Ost[(size_t)r0*68 + nt*8 + col0] =
            make_float2(o[nt][0]*inv0, o[nt][1]*inv0);
        *(float2*)&Ost[(size_t)(r0 + 8)*68 + nt*8 + col0] =
            make_float2(o[nt][2]*inv1, o[nt][3]*inv1);
    }
    __syncthreads();
    #pragma unroll
    for (int it = 0; it < 8; it++) {
        int idx = tid + it*256;
        int r = idx >> 4, c4 = (idx & 15)*4;
        float4 v = *(float4*)&Ost[(size_t)r*68 + c4];
        *(float4*)&out[((size_t)b*SEQ + q0 + r)*HIDDEN + h*HDIM + c4] = v;
    }
}

// ---------------------------------------------------------------------------
extern "C" void kernel_launch(void* const* d_in, const int* in_sizes, int n_in,
                              void* d_out, int out_size) {
    const float* hs   = (const float*)d_in[0];
    const float* mask = (const float*)d_in[1];
    const float* Wq = (const float*)d_in[2];
    const float* bq = (const float*)d_in[3];
    const float* Aq = (const float*)d_in[4];
    const float* Bq = (const float*)d_in[5];
    const float* Wk = (const float*)d_in[6];
    const float* bk = (const float*)d_in[7];
    const float* Ak = (const float*)d_in[8];
    const float* Bk = (const float*)d_in[9];
    const float* Wv = (const float*)d_in[10];
    const float* bv = (const float*)d_in[11];
    const float* Av = (const float*)d_in[12];
    const float* Bv = (const float*)d_in[13];
    float* out = (float*)d_out;

    static int attr_set = 0;
    if (!attr_set) {
        cudaFuncSetAttribute(qkv_gemm_mma,
            cudaFuncAttributeMaxDynamicSharedMemorySize, GEMM_SMEM);
        cudaFuncSetAttribute(attn_mma,
            cudaFuncAttributeMaxDynamicSharedMemorySize, AT_SMEM);
        attr_set = 1;
    }

    xsplit_kernel<<<NTOK*HIDDEN/1024, 256>>>(hs);
    wsplit_kernel<<<dim3(HIDDEN, 3), 256>>>(Wq, Aq, Bq, Wk, Ak, Bk, Wv, Av, Bv);

    {
        dim3 grid(3*HIDDEN/128, NTOK/256);
        qkv_gemm_mma<<<grid, 512, GEMM_SMEM>>>(bq, bk, bv);
    }
    {
        dim3 grid(SEQ/128, NBH);
        attn_mma<<<grid, 256, AT_SMEM>>>(mask, out);
    }
}

// round 15
// speedup vs baseline: 1.1257x; 1.1257x over previous
#include <cuda_runtime.h>
#include <cuda_bf16.h>
#include <cuda_fp16.h>
#include <cstdint>

#define HIDDEN 1024
#define HEADS  16
#define HDIM   64
#define RANK   16
#define SEQ    2048
#define BS     4
#define NTOK   (BS*SEQ)          /* 8192 */
#define NBH    (BS*HEADS)        /* 64 */
#define LOG2E  1.44269504088896340736f
#define ONES2  0x3C003C00u       /* f16x2 {1.0, 1.0} */

// ---------------- scratch (device globals; no allocation) -------------------
__device__ __align__(16) __half g_xh[(size_t)NTOK*HIDDEN];
__device__ __align__(16) __half g_wh[(size_t)3*HIDDEN*HIDDEN];
// Q (pre-scaled by 0.125*log2e), K, V: all single fp16, [bh][seq][64].
__device__ __align__(16) __half gQh[(size_t)NBH*SEQ*HDIM];
__device__ __align__(16) __half gKh[(size_t)NBH*SEQ*HDIM];
__device__ __align__(16) __half gVh[(size_t)NBH*SEQ*HDIM];

// ---------------- low-level helpers ----------------------------------------
__device__ __forceinline__ uint32_t smem_u32(const void* p) {
    uint32_t a;
    asm("{ .reg .u64 t; cvta.to.shared.u64 t, %1; cvt.u32.u64 %0, t; }"
        : "=r"(a) : "l"(p));
    return a;
}
__device__ __forceinline__ void cpa16(uint32_t dst, const void* src) {
    asm volatile("cp.async.cg.shared.global [%0],[%1],16;"
                 :: "r"(dst), "l"(__cvta_generic_to_global(src)));
}
#define CP_COMMIT() asm volatile("cp.async.commit_group;" ::: "memory")
#define CP_WAIT(n)  asm volatile("cp.async.wait_group %0;" :: "n"(n) : "memory")

#define SWZ(o)   ((o) ^ (((o) >> 3) & 0x70))   /* 128B rows */

__device__ __forceinline__ void ldsm4(uint32_t r[4], uint32_t a) {
    asm volatile("ldmatrix.sync.aligned.m8n8.x4.shared.b16 {%0,%1,%2,%3},[%4];"
        : "=r"(r[0]), "=r"(r[1]), "=r"(r[2]), "=r"(r[3]) : "r"(a));
}
__device__ __forceinline__ void ldsm4t(uint32_t r[4], uint32_t a) {
    asm volatile("ldmatrix.sync.aligned.m8n8.x4.trans.shared.b16 {%0,%1,%2,%3},[%4];"
        : "=r"(r[0]), "=r"(r[1]), "=r"(r[2]), "=r"(r[3]) : "r"(a));
}
// fp16 MMA
__device__ __forceinline__ void mma16816h(float c[4], const uint32_t a[4],
                                          uint32_t b0, uint32_t b1) {
    asm volatile(
        "mma.sync.aligned.m16n8k16.row.col.f32.f16.f16.f32 "
        "{%0,%1,%2,%3},{%4,%5,%6,%7},{%8,%9},{%0,%1,%2,%3};"
        : "+f"(c[0]), "+f"(c[1]), "+f"(c[2]), "+f"(c[3])
        : "r"(a[0]), "r"(a[1]), "r"(a[2]), "r"(a[3]), "r"(b0), "r"(b1));
}
__device__ __forceinline__ uint32_t pkhf(float x, float y) {
    uint32_t r;
    asm("cvt.rn.f16x2.f32 %0,%1,%2;" : "=r"(r) : "f"(y), "f"(x));
    return r;
}
__device__ __forceinline__ uint32_t hadd2(uint32_t a, uint32_t b) {
    uint32_t r;
    asm("add.f16x2 %0,%1,%2;" : "=r"(r) : "r"(a), "r"(b));
    return r;
}
__device__ __forceinline__ uint32_t ex2h2(uint32_t x) {
    uint32_t r;
    asm("ex2.approx.f16x2 %0,%1;" : "=r"(r) : "r"(x));
    return r;
}

// ---------------------------------------------------------------------------
// Kernel 1a: convert X to fp16.
// ---------------------------------------------------------------------------
__global__ void xsplit_kernel(const float* __restrict__ X) {
    size_t i = ((size_t)blockIdx.x * 256 + threadIdx.x) * 4;
    float4 v = *(const float4*)&X[i];
    *(uint2*)&g_xh[i] = make_uint2(pkhf(v.x, v.y), pkhf(v.z, v.w));
}

// ---------------------------------------------------------------------------
// Kernel 1b (fused): Weff = W + (1/16) B @ A, stored as single fp16.
// ---------------------------------------------------------------------------
__global__ void wsplit_kernel(
        const float* __restrict__ Wq, const float* __restrict__ Aq, const float* __restrict__ Bq,
        const float* __restrict__ Wk, const float* __restrict__ Ak, const float* __restrict__ Bk,
        const float* __restrict__ Wv, const float* __restrict__ Av, const float* __restrict__ Bv) {
    int p = blockIdx.y;
    const float* W = (p == 0) ? Wq : ((p == 1) ? Wk : Wv);
    const float* A = (p == 0) ? Aq : ((p == 1) ? Ak : Av);
    const float* B = (p == 0) ? Bq : ((p == 1) ? Bk : Bv);
    int n = blockIdx.x;
    __shared__ float Brow[RANK];
    if (threadIdx.x < RANK)
        Brow[threadIdx.x] = B[n*RANK + threadIdx.x] * (1.0f/RANK);
    __syncthreads();
    size_t roff = ((size_t)p*HIDDEN + n) * HIDDEN;
    const float* wr = W + (size_t)n*HIDDEN;
    for (int k = threadIdx.x; k < HIDDEN; k += blockDim.x) {
        float acc = wr[k];
        #pragma unroll
        for (int r = 0; r < RANK; r++)
            acc += Brow[r] * A[r*HIDDEN + k];
        g_wh[roff + k] = __float2half_rn(acc);
    }
}

// ---------------------------------------------------------------------------
// Kernel 2: QKV GEMM (REVERTED to round-12 config): fp16 single-term,
// tile 128x128, K-chunk 64, 2-stage, 256 threads, 2 CTAs/SM.
// ---------------------------------------------------------------------------
#define GTILE 16384                  /* 128 rows x 64 fp16 = 128B rows */
#define GSTAGE (2*GTILE)             /* 32 KB: Xh, Wh */
#define GEMM_SMEM 67584              /* max(2*GSTAGE=64K, epilogue 128*132*4) */

__global__ __launch_bounds__(256, 2) void qkv_gemm_mma(
        const float* __restrict__ bq,
        const float* __restrict__ bk,
        const float* __restrict__ bv) {
    extern __shared__ char smg[];
    uint32_t sb = smem_u32(smg);
    int tid = threadIdx.x, lane = tid & 31, wid = tid >> 5;
    int bm = blockIdx.y * 128, bn = blockIdx.x * 128;
    int wm = (wid >> 2) * 64, wn = (wid & 3) * 32;

    float acc[4][4][4];
    #pragma unroll
    for (int a = 0; a < 4; a++)
        #pragma unroll
        for (int b = 0; b < 4; b++)
            #pragma unroll
            for (int c = 0; c < 4; c++) acc[a][b][c] = 0.0f;

    auto load_stage = [&](int s, int c) {
        int k0 = c * 64;
        uint32_t base = sb + s * GSTAGE;
        #pragma unroll
        for (int it = 0; it < 4; it++) {
            int idx = tid + it*256;
            int r = idx >> 3, cb = (idx & 7) << 4;
            uint32_t so = SWZ(r*128 + cb);
            cpa16(base + so,         (const char*)(g_xh + (size_t)(bm + r)*HIDDEN + k0) + cb);
            cpa16(base + GTILE + so, (const char*)(g_wh + (size_t)(bn + r)*HIDDEN + k0) + cb);
        }
    };

    load_stage(0, 0); CP_COMMIT();

    for (int c = 0; c < 16; c++) {
        CP_WAIT(0);
        __syncthreads();
        if (c + 1 < 16) { load_stage((c + 1) & 1, c + 1); CP_COMMIT(); }

        uint32_t tb = sb + (c & 1) * GSTAGE;
        int arow = wm + (lane & 15);
        int bro  = wn + ((lane >> 4) & 1)*8 + (lane & 7);
        #pragma unroll
        for (int ks = 0; ks < 4; ks++) {
            int acb = ks*32 + ((lane >> 4) & 1)*16;
            int bcb = ks*32 + ((lane >> 3) & 1)*16;
            uint32_t ah[4][4];
            #pragma unroll
            for (int mt = 0; mt < 4; mt++)
                ldsm4(ah[mt], tb + SWZ((arow + mt*16)*128 + acb));
            #pragma unroll
            for (int nt2 = 0; nt2 < 2; nt2++) {
                uint32_t bh4[4];
                ldsm4(bh4, tb + GTILE + SWZ((bro + nt2*16)*128 + bcb));
                #pragma unroll
                for (int mt = 0; mt < 4; mt++) {
                    mma16816h(acc[mt][nt2*2],   ah[mt], bh4[0], bh4[1]);
                    mma16816h(acc[mt][nt2*2+1], ah[mt], bh4[2], bh4[3]);
                }
            }
        }
    }
    __syncthreads();   // all reads of stage smem done before epilogue reuse

    // stage C to smem f32 [128][132]
    float* st = (float*)smg;
    int r0 = lane >> 2, col0 = (lane & 3)*2;
    #pragma unroll
    for (int mt = 0; mt < 4; mt++)
        #pragma unroll
        for (int nt = 0; nt < 4; nt++) {
            int rr = wm + mt*16 + r0;
            int cc = wn + nt*8 + col0;
            *(float2*)&st[(size_t)rr*132 + cc]       = make_float2(acc[mt][nt][0], acc[mt][nt][1]);
            *(float2*)&st[(size_t)(rr + 8)*132 + cc] = make_float2(acc[mt][nt][2], acc[mt][nt][3]);
        }
    __syncthreads();

    int p    = bn >> 10;
    int coff = bn & 1023;
    const float* bias = (p == 0) ? bq : ((p == 1) ? bk : bv);
    float scale = (p == 0) ? 0.125f * LOG2E : 1.0f;
    __half* dst = (p == 0) ? gQh : ((p == 1) ? gKh : gVh);

    #pragma unroll
    for (int it = 0; it < 16; it++) {
        int idx = tid + it*256;
        int r = idx >> 5, c4 = (idx & 31)*4;
        float4 v = *(float4*)&st[(size_t)r*132 + c4];
        int colg = coff + c4;
        float4 bi = *(const float4*)&bias[colg];
        v.x = (v.x + bi.x)*scale; v.y = (v.y + bi.y)*scale;
        v.z = (v.z + bi.z)*scale; v.w = (v.w + bi.w)*scale;
        int m  = bm + r;
        int bb = m >> 11, sq = m & 2047;
        int h  = colg >> 6, d = colg & 63;
        size_t o = ((size_t)(bb*HEADS + h)*SEQ + sq)*HDIM + d;
        *(uint2*)&dst[o] = make_uint2(pkhf(v.x, v.y), pkhf(v.z, v.w));
    }
}

// ---------------------------------------------------------------------------
// Kernel 3: flash attention, 128 threads / 4 warps, 32 q rows per warp
// (halves LDS traffic per unit work). kv-chunk 128 (2-stage), no-max
// softmax per-nt2 slice, l via ones-MMA. 2 CTAs/SM.
// ---------------------------------------------------------------------------
#define AKT2 16384                    /* one 128x64 fp16 KV tile */
#define AQT 16384                     /* one 128x64 fp16 Q tile */
#define AT_Q 4096                     /* after 4KB fp16 mask */
#define AT_KV (AT_Q + AQT)            /* 20480 */
#define AT_STG (2*AKT2)               /* 32768: Kh,Vh */
#define AT_SMEM (AT_KV + 2*AT_STG)    /* 86016 */

__global__ __launch_bounds__(128, 2) void attn_mma(
        const float* __restrict__ mask,
        float* __restrict__ out) {
    extern __shared__ char sma[];
    uint32_t sb = smem_u32(sma);
    int tid = threadIdx.x, lane = tid & 31, wid = tid >> 5;
    int bh = blockIdx.y;
    int b = bh >> 4, h = bh & 15;
    int q0 = blockIdx.x * 128;

    // mask row -> smem as f16x2, premultiplied by log2e
    __half* Msh = (__half*)sma;
    #pragma unroll
    for (int it = 0; it < 4; it++) {
        int i4 = (tid + it*128)*4;
        float4 v = *(const float4*)&mask[(size_t)b*SEQ + i4];
        *(uint32_t*)&Msh[i4]   = pkhf(v.x*LOG2E, v.y*LOG2E);
        *(uint32_t*)&Msh[i4+2] = pkhf(v.z*LOG2E, v.w*LOG2E);
    }
    // Q tile (128x64 fp16) -> smem
    {
        const char* qh = (const char*)(gQh + ((size_t)bh*SEQ + q0)*HDIM);
        #pragma unroll
        for (int it = 0; it < 8; it++) {
            int idx = tid + it*128;
            int r = idx >> 3, cb = (idx & 7) << 4;
            uint32_t so = SWZ(r*128 + cb);
            *(uint4*)(sma + AT_Q + so) = *(const uint4*)(qh + r*128 + cb);
        }
    }

    auto load_kv = [&](int s, int c) {
        size_t roff = ((size_t)bh*SEQ + c*128)*HDIM;
        uint32_t base = sb + AT_KV + s*AT_STG;
        const char* kh = (const char*)(gKh + roff);
        const char* vh = (const char*)(gVh + roff);
        #pragma unroll
        for (int it = 0; it < 8; it++) {
            int idx = tid + it*128;
            int r = idx >> 3, cb = (idx & 7) << 4;
            uint32_t so = SWZ(r*128 + cb);
            cpa16(base + so,        kh + r*128 + cb);
            cpa16(base + AKT2 + so, vh + r*128 + cb);
        }
    };

    load_kv(0, 0); CP_COMMIT();
    __syncthreads();   // Q + mask visible

    // persistent Q fragments: 2 m-tiles x 4 k-steps (32 regs)
    uint32_t qf[2][4][4];
    {
        int arow = wid*32 + (lane & 15);
        #pragma unroll
        for (int mt = 0; mt < 2; mt++)
            #pragma unroll
            for (int ks = 0; ks < 4; ks++) {
                int acb = ks*32 + ((lane >> 4) & 1)*16;
                ldsm4(qf[mt][ks], sb + AT_Q + SWZ((arow + mt*16)*128 + acb));
            }
    }

    float o[2][8][4];
    #pragma unroll
    for (int mt = 0; mt < 2; mt++)
        #pragma unroll
        for (int i = 0; i < 8; i++)
            #pragma unroll
            for (int j = 0; j < 4; j++) o[mt][i][j] = 0.0f;
    float lsum[2][4];
    #pragma unroll
    for (int mt = 0; mt < 2; mt++)
        #pragma unroll
        for (int j = 0; j < 4; j++) lsum[mt][j] = 0.0f;

    int bro  = (lane & 7) + ((lane >> 4) & 1)*8;
    int col0 = (lane & 3)*2;

    for (int c = 0; c < 16; c++) {
        CP_WAIT(0);
        __syncthreads();
        if (c + 1 < 16) { load_kv((c + 1) & 1, c + 1); CP_COMMIT(); }

        uint32_t stg = sb + AT_KV + (c & 1)*AT_STG;

        #pragma unroll
        for (int half = 0; half < 2; half++) {
            uint32_t kb = stg + half*8192;            // 64 rows x 128B
            uint32_t vb = stg + AKT2 + half*8192;
            int ckv = c*128 + half*64;

            #pragma unroll
            for (int nt2 = 0; nt2 < 4; nt2++) {
                // ---- S slice: 32 q rows x 16 keys ----
                float sc[2][2][4];
                #pragma unroll
                for (int mt = 0; mt < 2; mt++)
                    #pragma unroll
                    for (int g = 0; g < 2; g++)
                        #pragma unroll
                        for (int j = 0; j < 4; j++) sc[mt][g][j] = 0.0f;

                #pragma unroll
                for (int ks = 0; ks < 4; ks++) {
                    int bcb = ks*32 + ((lane >> 3) & 1)*16;
                    uint32_t kh4[4];
                    ldsm4(kh4, kb + SWZ((nt2*16 + bro)*128 + bcb));
                    #pragma unroll
                    for (int mt = 0; mt < 2; mt++) {
                        mma16816h(sc[mt][0], qf[mt][ks], kh4[0], kh4[1]);
                        mma16816h(sc[mt][1], qf[mt][ks], kh4[2], kh4[3]);
                    }
                }

                // ---- P = 2^(s+mask) (f16x2), lsum MMA ----
                uint32_t mk0 = *(uint32_t*)&Msh[ckv + nt2*16 + col0];
                uint32_t mk1 = *(uint32_t*)&Msh[ckv + nt2*16 + 8 + col0];
                uint32_t ph[2][4];
                #pragma unroll
                for (int mt = 0; mt < 2; mt++) {
                    float* e = sc[mt][0];
                    float* f = sc[mt][1];
                    ph[mt][0] = ex2h2(hadd2(pkhf(e[0], e[1]), mk0));
                    ph[mt][1] = ex2h2(hadd2(pkhf(e[2], e[3]), mk0));
                    ph[mt][2] = ex2h2(hadd2(pkhf(f[0], f[1]), mk1));
                    ph[mt][3] = ex2h2(hadd2(pkhf(f[2], f[3]), mk1));
                    mma16816h(lsum[mt], ph[mt], ONES2, ONES2);
                }

                // ---- O += P V (V fragments shared across both m-tiles) ----
                int vrow = nt2*16 + (lane & 15);
                uint32_t vh4[4][4];
                #pragma unroll
                for (int dt2 = 0; dt2 < 4; dt2++) {
                    int vcb = dt2*32 + ((lane >> 4) & 1)*16;
                    ldsm4t(vh4[dt2], vb + SWZ(vrow*128 + vcb));
                }
                #pragma unroll
                for (int mt = 0; mt < 2; mt++)
                    #pragma unroll
                    for (int dt2 = 0; dt2 < 4; dt2++) {
                        mma16816h(o[mt][dt2*2],   ph[mt], vh4[dt2][0], vh4[dt2][1]);
                        mma16816h(o[mt][dt2*2+1], ph[mt], vh4[dt2][2], vh4[dt2][3]);
                    }
            }
        }
    }
    __syncthreads();   // all smem reads done before epilogue reuse

    // ---- epilogue: normalize, stage (128x68 f32), write ----
    float* Ost = (float*)sma;
    #pragma unroll
    for (int mt = 0; mt < 2; mt++) {
        float inv0 = 1.0f / lsum[mt][0], inv1 = 1.0f / lsum[mt][2];
        int r0 = wid*32 + mt*16 + (lane >> 2);
        #pragma unroll
        for (int nt = 0; nt < 8; nt++) {
            *(float2*)&Ost[(size_t)r0*68 + nt*8 + col0] =
                make_float2(o[mt][nt][0]*inv0, o[mt][nt][1]*inv0);
            *(float2*)&Ost[(size_t)(r0 + 8)*68 + nt*8 + col0] =
                make_float2(o[mt][nt][2]*inv1, o[mt][nt][3]*inv1);
        }
    }
    __syncthreads();
    #pragma unroll
    for (int it = 0; it < 16; it++) {
        int idx = tid + it*128;
        int r = idx >> 4, c4 = (idx & 15)*4;
        float4 v = *(float4*)&Ost[(size_t)r*68 + c4];
        *(float4*)&out[((size_t)b*SEQ + q0 + r)*HIDDEN + h*HDIM + c4] = v;
    }
}

// ---------------------------------------------------------------------------
extern "C" void kernel_launch(void* const* d_in, const int* in_sizes, int n_in,
                              void* d_out, int out_size) {
    const float* hs   = (const float*)d_in[0];
    const float* mask = (const float*)d_in[1];
    const float* Wq = (const float*)d_in[2];
    const float* bq = (const float*)d_in[3];
    const float* Aq = (const float*)d_in[4];
    const float* Bq = (const float*)d_in[5];
    const float* Wk = (const float*)d_in[6];
    const float* bk = (const float*)d_in[7];
    const float* Ak = (const float*)d_in[8];
    const float* Bk = (const float*)d_in[9];
    const float* Wv = (const float*)d_in[10];
    const float* bv = (const float*)d_in[11];
    const float* Av = (const float*)d_in[12];
    const float* Bv = (const float*)d_in[13];
    float* out = (float*)d_out;

    static int attr_set = 0;
    if (!attr_set) {
        cudaFuncSetAttribute(qkv_gemm_mma,
            cudaFuncAttributeMaxDynamicSharedMemorySize, GEMM_SMEM);
        cudaFuncSetAttribute(attn_mma,
            cudaFuncAttributeMaxDynamicSharedMemorySize, AT_SMEM);
        attr_set = 1;
    }

    xsplit_kernel<<<NTOK*HIDDEN/1024, 256>>>(hs);
    wsplit_kernel<<<dim3(HIDDEN, 3), 256>>>(Wq, Aq, Bq, Wk, Ak, Bk, Wv, Av, Bv);

    {
        dim3 grid(3*HIDDEN/128, NTOK/128);
        qkv_gemm_mma<<<grid, 256, GEMM_SMEM>>>(bq, bk, bv);
    }
    {
        dim3 grid(SEQ/128, NBH);
        attn_mma<<<grid, 128, AT_SMEM>>>(mask, out);
    }
}

// round 16
// speedup vs baseline: 1.1610x; 1.0314x over previous
#include <cuda_runtime.h>
#include <cuda_bf16.h>
#include <cuda_fp16.h>
#include <cstdint>

#define HIDDEN 1024
#define HEADS  16
#define HDIM   64
#define RANK   16
#define SEQ    2048
#define BS     4
#define NTOK   (BS*SEQ)          /* 8192 */
#define NBH    (BS*HEADS)        /* 64 */
#define LOG2E  1.44269504088896340736f
#define ONES2  0x3C003C00u       /* f16x2 {1.0, 1.0} */

// ---------------- scratch (device globals; no allocation) -------------------
__device__ __align__(16) __half g_xh[(size_t)NTOK*HIDDEN];
__device__ __align__(16) __half g_wh[(size_t)3*HIDDEN*HIDDEN];
// Q (pre-scaled by 0.125*log2e), K, V: all single fp16, [bh][seq][64].
__device__ __align__(16) __half gQh[(size_t)NBH*SEQ*HDIM];
__device__ __align__(16) __half gKh[(size_t)NBH*SEQ*HDIM];
__device__ __align__(16) __half gVh[(size_t)NBH*SEQ*HDIM];

// ---------------- low-level helpers ----------------------------------------
__device__ __forceinline__ uint32_t smem_u32(const void* p) {
    uint32_t a;
    asm("{ .reg .u64 t; cvta.to.shared.u64 t, %1; cvt.u32.u64 %0, t; }"
        : "=r"(a) : "l"(p));
    return a;
}
__device__ __forceinline__ void cpa16(uint32_t dst, const void* src) {
    asm volatile("cp.async.cg.shared.global [%0],[%1],16;"
                 :: "r"(dst), "l"(__cvta_generic_to_global(src)));
}
#define CP_COMMIT() asm volatile("cp.async.commit_group;" ::: "memory")
#define CP_WAIT(n)  asm volatile("cp.async.wait_group %0;" :: "n"(n) : "memory")

#define SWZ(o)   ((o) ^ (((o) >> 3) & 0x70))   /* 128B rows */

__device__ __forceinline__ void ldsm4(uint32_t r[4], uint32_t a) {
    asm volatile("ldmatrix.sync.aligned.m8n8.x4.shared.b16 {%0,%1,%2,%3},[%4];"
        : "=r"(r[0]), "=r"(r[1]), "=r"(r[2]), "=r"(r[3]) : "r"(a));
}
__device__ __forceinline__ void ldsm4t(uint32_t r[4], uint32_t a) {
    asm volatile("ldmatrix.sync.aligned.m8n8.x4.trans.shared.b16 {%0,%1,%2,%3},[%4];"
        : "=r"(r[0]), "=r"(r[1]), "=r"(r[2]), "=r"(r[3]) : "r"(a));
}
// fp16 MMA
__device__ __forceinline__ void mma16816h(float c[4], const uint32_t a[4],
                                          uint32_t b0, uint32_t b1) {
    asm volatile(
        "mma.sync.aligned.m16n8k16.row.col.f32.f16.f16.f32 "
        "{%0,%1,%2,%3},{%4,%5,%6,%7},{%8,%9},{%0,%1,%2,%3};"
        : "+f"(c[0]), "+f"(c[1]), "+f"(c[2]), "+f"(c[3])
        : "r"(a[0]), "r"(a[1]), "r"(a[2]), "r"(a[3]), "r"(b0), "r"(b1));
}
__device__ __forceinline__ uint32_t pkhf(float x, float y) {
    uint32_t r;
    asm("cvt.rn.f16x2.f32 %0,%1,%2;" : "=r"(r) : "f"(y), "f"(x));
    return r;
}
__device__ __forceinline__ uint32_t hadd2(uint32_t a, uint32_t b) {
    uint32_t r;
    asm("add.f16x2 %0,%1,%2;" : "=r"(r) : "r"(a), "r"(b));
    return r;
}
__device__ __forceinline__ uint32_t ex2h2(uint32_t x) {
    uint32_t r;
    asm("ex2.approx.f16x2 %0,%1;" : "=r"(r) : "r"(x));
    return r;
}

// ---------------------------------------------------------------------------
// Kernel 1a: convert X to fp16.
// ---------------------------------------------------------------------------
__global__ void xsplit_kernel(const float* __restrict__ X) {
    size_t i = ((size_t)blockIdx.x * 256 + threadIdx.x) * 4;
    float4 v = *(const float4*)&X[i];
    *(uint2*)&g_xh[i] = make_uint2(pkhf(v.x, v.y), pkhf(v.z, v.w));
}

// ---------------------------------------------------------------------------
// Kernel 1b: Weff = W + (1/16) B @ A, fp16 out. 16 n-rows per block with
// A (64KB) + B staged in smem once (cuts A re-read L2 traffic 192MB -> 25MB).
// grid (64, 3) x 256.
// ---------------------------------------------------------------------------
#define WSPLIT_SMEM (RANK*HIDDEN*4 + 16*RANK*4)   /* 64KB A + 1KB B */

__global__ void wsplit_kernel(
        const float* __restrict__ Wq, const float* __restrict__ Aq, const float* __restrict__ Bq,
        const float* __restrict__ Wk, const float* __restrict__ Ak, const float* __restrict__ Bk,
        const float* __restrict__ Wv, const float* __restrict__ Av, const float* __restrict__ Bv) {
    extern __shared__ float wsm[];
    float* As = wsm;                 // [RANK][HIDDEN]
    float* Bs = wsm + RANK*HIDDEN;   // [16][RANK]
    int p = blockIdx.y;
    const float* W = (p == 0) ? Wq : ((p == 1) ? Wk : Wv);
    const float* A = (p == 0) ? Aq : ((p == 1) ? Ak : Av);
    const float* B = (p == 0) ? Bq : ((p == 1) ? Bk : Bv);
    int n0 = blockIdx.x * 16;
    int tid = threadIdx.x;

    // stage A (16384 floats, float4 x 16 per thread)
    #pragma unroll
    for (int it = 0; it < 16; it++) {
        int i4 = (tid + it*256)*4;
        *(float4*)&As[i4] = *(const float4*)&A[i4];
    }
    // stage B rows n0..n0+15, pre-scaled
    if (tid < 16*RANK)
        Bs[tid] = B[(n0 + (tid >> 4))*RANK + (tid & 15)] * (1.0f/RANK);
    __syncthreads();

    for (int nr = 0; nr < 16; nr++) {
        int n = n0 + nr;
        size_t roff = ((size_t)p*HIDDEN + n) * HIDDEN;
        const float* wr = W + (size_t)n*HIDDEN;
        const float* Brow = &Bs[nr*RANK];
        #pragma unroll
        for (int it = 0; it < 4; it++) {
            int k = tid + it*256;
            float acc = wr[k];
            #pragma unroll
            for (int r = 0; r < RANK; r++)
                acc += Brow[r] * As[r*HIDDEN + k];
            g_wh[roff + k] = __float2half_rn(acc);
        }
    }
}

// ---------------------------------------------------------------------------
// Kernel 2: QKV GEMM: fp16 single-term, tile 128x128, K-chunk 64, 2-stage,
// 256 threads, 2 CTAs/SM. Direct register->gmem fp16 epilogue (no staging).
// ---------------------------------------------------------------------------
#define GTILE 16384                  /* 128 rows x 64 fp16 = 128B rows */
#define GSTAGE (2*GTILE)             /* 32 KB: Xh, Wh */
#define GEMM_SMEM (2*GSTAGE)         /* 64 KB */

__global__ __launch_bounds__(256, 2) void qkv_gemm_mma(
        const float* __restrict__ bq,
        const float* __restrict__ bk,
        const float* __restrict__ bv) {
    extern __shared__ char smg[];
    uint32_t sb = smem_u32(smg);
    int tid = threadIdx.x, lane = tid & 31, wid = tid >> 5;
    int bm = blockIdx.y * 128, bn = blockIdx.x * 128;
    int wm = (wid >> 2) * 64, wn = (wid & 3) * 32;

    float acc[4][4][4];
    #pragma unroll
    for (int a = 0; a < 4; a++)
        #pragma unroll
        for (int b = 0; b < 4; b++)
            #pragma unroll
            for (int c = 0; c < 4; c++) acc[a][b][c] = 0.0f;

    auto load_stage = [&](int s, int c) {
        int k0 = c * 64;
        uint32_t base = sb + s * GSTAGE;
        #pragma unroll
        for (int it = 0; it < 4; it++) {
            int idx = tid + it*256;
            int r = idx >> 3, cb = (idx & 7) << 4;
            uint32_t so = SWZ(r*128 + cb);
            cpa16(base + so,         (const char*)(g_xh + (size_t)(bm + r)*HIDDEN + k0) + cb);
            cpa16(base + GTILE + so, (const char*)(g_wh + (size_t)(bn + r)*HIDDEN + k0) + cb);
        }
    };

    load_stage(0, 0); CP_COMMIT();

    for (int c = 0; c < 16; c++) {
        CP_WAIT(0);
        __syncthreads();
        if (c + 1 < 16) { load_stage((c + 1) & 1, c + 1); CP_COMMIT(); }

        uint32_t tb = sb + (c & 1) * GSTAGE;
        int arow = wm + (lane & 15);
        int bro  = wn + ((lane >> 4) & 1)*8 + (lane & 7);
        #pragma unroll
        for (int ks = 0; ks < 4; ks++) {
            int acb = ks*32 + ((lane >> 4) & 1)*16;
            int bcb = ks*32 + ((lane >> 3) & 1)*16;
            uint32_t ah[4][4];
            #pragma unroll
            for (int mt = 0; mt < 4; mt++)
                ldsm4(ah[mt], tb + SWZ((arow + mt*16)*128 + acb));
            #pragma unroll
            for (int nt2 = 0; nt2 < 2; nt2++) {
                uint32_t bh4[4];
                ldsm4(bh4, tb + GTILE + SWZ((bro + nt2*16)*128 + bcb));
                #pragma unroll
                for (int mt = 0; mt < 4; mt++) {
                    mma16816h(acc[mt][nt2*2],   ah[mt], bh4[0], bh4[1]);
                    mma16816h(acc[mt][nt2*2+1], ah[mt], bh4[2], bh4[3]);
                }
            }
        }
    }

    // ---- direct register -> gmem fp16 epilogue (no smem staging) ----
    int p    = bn >> 10;
    int coff = bn & 1023;
    const float* bias = (p == 0) ? bq : ((p == 1) ? bk : bv);
    float scale = (p == 0) ? 0.125f * LOG2E : 1.0f;
    __half* dst = (p == 0) ? gQh : ((p == 1) ? gKh : gVh);

    int r0 = lane >> 2, col0 = (lane & 3)*2;
    #pragma unroll
    for (int nt = 0; nt < 4; nt++) {
        int colg = coff + wn + nt*8 + col0;            // within one head block
        float2 bi = *(const float2*)&bias[colg];
        int h = colg >> 6, d = colg & 63;
        #pragma unroll
        for (int mt = 0; mt < 4; mt++) {
            #pragma unroll
            for (int half = 0; half < 2; half++) {
                int m  = bm + wm + mt*16 + r0 + half*8;
                int bb = m >> 11, sq = m & 2047;
                float v0 = (acc[mt][nt][2*half+0] + bi.x)*scale;
                float v1 = (acc[mt][nt][2*half+1] + bi.y)*scale;
                size_t o = ((size_t)(bb*HEADS + h)*SEQ + sq)*HDIM + d;
                *(uint32_t*)&dst[o] = pkhf(v0, v1);
            }
        }
    }
}

// ---------------------------------------------------------------------------
// Kernel 3: flash attention (unchanged from round 15): 128 thr / 4 warps,
// 32 q rows per warp, kv-chunk 128 2-stage, no-max f16x2 softmax, 2 CTAs/SM.
// ---------------------------------------------------------------------------
#define AKT2 16384                    /* one 128x64 fp16 KV tile */
#define AQT 16384                     /* one 128x64 fp16 Q tile */
#define AT_Q 4096                     /* after 4KB fp16 mask */
#define AT_KV (AT_Q + AQT)            /* 20480 */
#define AT_STG (2*AKT2)               /* 32768: Kh,Vh */
#define AT_SMEM (AT_KV + 2*AT_STG)    /* 86016 */

__global__ __launch_bounds__(128, 2) void attn_mma(
        const float* __restrict__ mask,
        float* __restrict__ out) {
    extern __shared__ char sma[];
    uint32_t sb = smem_u32(sma);
    int tid = threadIdx.x, lane = tid & 31, wid = tid >> 5;
    int bh = blockIdx.y;
    int b = bh >> 4, h = bh & 15;
    int q0 = blockIdx.x * 128;

    __half* Msh = (__half*)sma;
    #pragma unroll
    for (int it = 0; it < 4; it++) {
        int i4 = (tid + it*128)*4;
        float4 v = *(const float4*)&mask[(size_t)b*SEQ + i4];
        *(uint32_t*)&Msh[i4]   = pkhf(v.x*LOG2E, v.y*LOG2E);
        *(uint32_t*)&Msh[i4+2] = pkhf(v.z*LOG2E, v.w*LOG2E);
    }
    {
        const char* qh = (const char*)(gQh + ((size_t)bh*SEQ + q0)*HDIM);
        #pragma unroll
        for (int it = 0; it < 8; it++) {
            int idx = tid + it*128;
            int r = idx >> 3, cb = (idx & 7) << 4;
            uint32_t so = SWZ(r*128 + cb);
            *(uint4*)(sma + AT_Q + so) = *(const uint4*)(qh + r*128 + cb);
        }
    }

    auto load_kv = [&](int s, int c) {
        size_t roff = ((size_t)bh*SEQ + c*128)*HDIM;
        uint32_t base = sb + AT_KV + s*AT_STG;
        const char* kh = (const char*)(gKh + roff);
        const char* vh = (const char*)(gVh + roff);
        #pragma unroll
        for (int it = 0; it < 8; it++) {
            int idx = tid + it*128;
            int r = idx >> 3, cb = (idx & 7) << 4;
            uint32_t so = SWZ(r*128 + cb);
            cpa16(base + so,        kh + r*128 + cb);
            cpa16(base + AKT2 + so, vh + r*128 + cb);
        }
    };

    load_kv(0, 0); CP_COMMIT();
    __syncthreads();

    uint32_t qf[2][4][4];
    {
        int arow = wid*32 + (lane & 15);
        #pragma unroll
        for (int mt = 0; mt < 2; mt++)
            #pragma unroll
            for (int ks = 0; ks < 4; ks++) {
                int acb = ks*32 + ((lane >> 4) & 1)*16;
                ldsm4(qf[mt][ks], sb + AT_Q + SWZ((arow + mt*16)*128 + acb));
            }
    }

    float o[2][8][4];
    #pragma unroll
    for (int mt = 0; mt < 2; mt++)
        #pragma unroll
        for (int i = 0; i < 8; i++)
            #pragma unroll
            for (int j = 0; j < 4; j++) o[mt][i][j] = 0.0f;
    float lsum[2][4];
    #pragma unroll
    for (int mt = 0; mt < 2; mt++)
        #pragma unroll
        for (int j = 0; j < 4; j++) lsum[mt][j] = 0.0f;

    int bro  = (lane & 7) + ((lane >> 4) & 1)*8;
    int col0 = (lane & 3)*2;

    for (int c = 0; c < 16; c++) {
        CP_WAIT(0);
        __syncthreads();
        if (c + 1 < 16) { load_kv((c + 1) & 1, c + 1); CP_COMMIT(); }

        uint32_t stg = sb + AT_KV + (c & 1)*AT_STG;

        #pragma unroll
        for (int half = 0; half < 2; half++) {
            uint32_t kb = stg + half*8192;
            uint32_t vb = stg + AKT2 + half*8192;
            int ckv = c*128 + half*64;

            #pragma unroll
            for (int nt2 = 0; nt2 < 4; nt2++) {
                float sc[2][2][4];
                #pragma unroll
                for (int mt = 0; mt < 2; mt++)
                    #pragma unroll
                    for (int g = 0; g < 2; g++)
                        #pragma unroll
                        for (int j = 0; j < 4; j++) sc[mt][g][j] = 0.0f;

                #pragma unroll
                for (int ks = 0; ks < 4; ks++) {
                    int bcb = ks*32 + ((lane >> 3) & 1)*16;
                    uint32_t kh4[4];
                    ldsm4(kh4, kb + SWZ((nt2*16 + bro)*128 + bcb));
                    #pragma unroll
                    for (int mt = 0; mt < 2; mt++) {
                        mma16816h(sc[mt][0], qf[mt][ks], kh4[0], kh4[1]);
                        mma16816h(sc[mt][1], qf[mt][ks], kh4[2], kh4[3]);
                    }
                }

                uint32_t mk0 = *(uint32_t*)&Msh[ckv + nt2*16 + col0];
                uint32_t mk1 = *(uint32_t*)&Msh[ckv + nt2*16 + 8 + col0];
                uint32_t ph[2][4];
                #pragma unroll
                for (int mt = 0; mt < 2; mt++) {
                    float* e = sc[mt][0];
                    float* f = sc[mt][1];
                    ph[mt][0] = ex2h2(hadd2(pkhf(e[0], e[1]), mk0));
                    ph[mt][1] = ex2h2(hadd2(pkhf(e[2], e[3]), mk0));
                    ph[mt][2] = ex2h2(hadd2(pkhf(f[0], f[1]), mk1));
                    ph[mt][3] = ex2h2(hadd2(pkhf(f[2], f[3]), mk1));
                    mma16816h(lsum[mt], ph[mt], ONES2, ONES2);
                }

                int vrow = nt2*16 + (lane & 15);
                uint32_t vh4[4][4];
                #pragma unroll
                for (int dt2 = 0; dt2 < 4; dt2++) {
                    int vcb = dt2*32 + ((lane >> 4) & 1)*16;
                    ldsm4t(vh4[dt2], vb + SWZ(vrow*128 + vcb));
                }
                #pragma unroll
                for (int mt = 0; mt < 2; mt++)
                    #pragma unroll
                    for (int dt2 = 0; dt2 < 4; dt2++) {
                        mma16816h(o[mt][dt2*2],   ph[mt], vh4[dt2][0], vh4[dt2][1]);
                        mma16816h(o[mt][dt2*2+1], ph[mt], vh4[dt2][2], vh4[dt2][3]);
                    }
            }
        }
    }
    __syncthreads();

    float* Ost = (float*)sma;
    #pragma unroll
    for (int mt = 0; mt < 2; mt++) {
        float inv0 = 1.0f / lsum[mt][0], inv1 = 1.0f / lsum[mt][2];
        int r0 = wid*32 + mt*16 + (lane >> 2);
        #pragma unroll
        for (int nt = 0; nt < 8; nt++) {
            *(float2*)&Ost[(size_t)r0*68 + nt*8 + col0] =
                make_float2(o[mt][nt][0]*inv0, o[mt][nt][1]*inv0);
            *(float2*)&Ost[(size_t)(r0 + 8)*68 + nt*8 + col0] =
                make_float2(o[mt][nt][2]*inv1, o[mt][nt][3]*inv1);
        }
    }
    __syncthreads();
    #pragma unroll
    for (int it = 0; it < 16; it++) {
        int idx = tid + it*128;
        int r = idx >> 4, c4 = (idx & 15)*4;
        float4 v = *(float4*)&Ost[(size_t)r*68 + c4];
        *(float4*)&out[((size_t)b*SEQ + q0 + r)*HIDDEN + h*HDIM + c4] = v;
    }
}

// ---------------------------------------------------------------------------
extern "C" void kernel_launch(void* const* d_in, const int* in_sizes, int n_in,
                              void* d_out, int out_size) {
    const float* hs   = (const float*)d_in[0];
    const float* mask = (const float*)d_in[1];
    const float* Wq = (const float*)d_in[2];
    const float* bq = (const float*)d_in[3];
    const float* Aq = (const float*)d_in[4];
    const float* Bq = (const float*)d_in[5];
    const float* Wk = (const float*)d_in[6];
    const float* bk = (const float*)d_in[7];
    const float* Ak = (const float*)d_in[8];
    const float* Bk = (const float*)d_in[9];
    const float* Wv = (const float*)d_in[10];
    const float* bv = (const float*)d_in[11];
    const float* Av = (const float*)d_in[12];
    const float* Bv = (const float*)d_in[13];
    float* out = (float*)d_out;

    static int attr_set = 0;
    if (!attr_set) {
        cudaFuncSetAttribute(wsplit_kernel,
            cudaFuncAttributeMaxDynamicSharedMemorySize, WSPLIT_SMEM);
        cudaFuncSetAttribute(qkv_gemm_mma,
            cudaFuncAttributeMaxDynamicSharedMemorySize, GEMM_SMEM);
        cudaFuncSetAttribute(attn_mma,
            cudaFuncAttributeMaxDynamicSharedMemorySize, AT_SMEM);
        attr_set = 1;
    }

    xsplit_kernel<<<NTOK*HIDDEN/1024, 256>>>(hs);
    wsplit_kernel<<<dim3(64, 3), 256, WSPLIT_SMEM>>>(
        Wq, Aq, Bq, Wk, Ak, Bk, Wv, Av, Bv);

    {
        dim3 grid(3*HIDDEN/128, NTOK/128);
        qkv_gemm_mma<<<grid, 256, GEMM_SMEM>>>(bq, bk, bv);
    }
    {
        dim3 grid(SEQ/128, NBH);
        attn_mma<<<grid, 128, AT_SMEM>>>(mask, out);
    }
}